// round 2
// baseline (speedup 1.0000x reference)
#include <cuda_runtime.h>
#include <cstdint>

// Problem dims (fixed by the dataset)
#define BATCH 64
#define TT    1000
#define DIN   256
#define NN    512

#define THR_F   1.0f
#define TAU_F   20.0f
#define DT_F    1.0f

// Scratch: feed-forward currents [B*T, N] and transposed recurrent matrix
__device__ float g_incur[(size_t)BATCH * TT * NN];   // 131 MB
__device__ float g_Rt[NN * NN];                      // Rt[j*NN + n] = R[n*NN + j]

// ---------------------------------------------------------------------------
// Transpose R (512x512) so the scan can read spike-row contributions coalesced
// ---------------------------------------------------------------------------
__global__ void transpose_R_kernel(const float* __restrict__ R) {
    __shared__ float tile[32][33];
    int x = blockIdx.x * 32 + threadIdx.x;
    int y = blockIdx.y * 32 + threadIdx.y;
    tile[threadIdx.y][threadIdx.x] = R[y * NN + x];
    __syncthreads();
    int xo = blockIdx.y * 32 + threadIdx.x;
    int yo = blockIdx.x * 32 + threadIdx.y;
    g_Rt[yo * NN + xo] = tile[threadIdx.x][threadIdx.y];
}

// ---------------------------------------------------------------------------
// GEMM: in_cur[m, n] = sum_k x[m,k] * W[n,k] + b[n]
// M = 64000, K = 256, N = 512. Exact fp32. 128x128 tile, 8x8 per thread.
// ---------------------------------------------------------------------------
__global__ __launch_bounds__(256) void gemm_kernel(const float* __restrict__ A,
                                                   const float* __restrict__ W,
                                                   const float* __restrict__ bias) {
    __shared__ float As[8][128];
    __shared__ float Bs[8][128];

    const int tid  = threadIdx.x;
    const int bm   = blockIdx.x * 128;
    const int bn   = blockIdx.y * 128;

    // Loader mapping: 256 threads, each loads one float4 of the 128x8 tile
    const int lrow = tid >> 1;          // 0..127
    const int lcol = (tid & 1) << 2;    // 0 or 4

    const float* Aptr = A + (size_t)(bm + lrow) * DIN + lcol;
    const float* Wptr = W + (size_t)(bn + lrow) * DIN + lcol;

    // Compute mapping: 16x16 thread grid, 8x8 micro-tile
    const int ty = tid >> 4;
    const int tx = tid & 15;
    const int rm = ty * 8;
    const int rn = tx * 8;

    float acc[8][8];
#pragma unroll
    for (int i = 0; i < 8; i++)
#pragma unroll
        for (int j = 0; j < 8; j++) acc[i][j] = 0.0f;

    for (int k0 = 0; k0 < DIN; k0 += 8) {
        float4 av = *(const float4*)(Aptr + k0);
        float4 wv = *(const float4*)(Wptr + k0);
        As[lcol + 0][lrow] = av.x;
        As[lcol + 1][lrow] = av.y;
        As[lcol + 2][lrow] = av.z;
        As[lcol + 3][lrow] = av.w;
        Bs[lcol + 0][lrow] = wv.x;
        Bs[lcol + 1][lrow] = wv.y;
        Bs[lcol + 2][lrow] = wv.z;
        Bs[lcol + 3][lrow] = wv.w;
        __syncthreads();

#pragma unroll
        for (int k = 0; k < 8; k++) {
            float a[8], b[8];
#pragma unroll
            for (int i = 0; i < 8; i++) a[i] = As[k][rm + i];
#pragma unroll
            for (int j = 0; j < 8; j++) b[j] = Bs[k][rn + j];
#pragma unroll
            for (int i = 0; i < 8; i++)
#pragma unroll
                for (int j = 0; j < 8; j++) acc[i][j] += a[i] * b[j];
        }
        __syncthreads();
    }

    float bv[8];
#pragma unroll
    for (int j = 0; j < 8; j++) bv[j] = __ldg(&bias[bn + rn + j]);

#pragma unroll
    for (int i = 0; i < 8; i++) {
        size_t row = (size_t)(bm + rm + i) * NN + bn + rn;
#pragma unroll
        for (int j = 0; j < 8; j++) g_incur[row + j] = acc[i][j] + bv[j];
    }
}

// ---------------------------------------------------------------------------
// Sequential LIF scan. One block per batch element, one thread per neuron.
// Recurrent term handled via binary spike mask in shared memory (sparse).
// Writes outputs [B,T,N], u_all [B,T+1,N], z_all [B,T+1,N] into d_out.
// ---------------------------------------------------------------------------
__global__ __launch_bounds__(NN) void scan_kernel(float* __restrict__ out) {
    const int b = blockIdx.x;
    const int n = threadIdx.x;
    const int lane = n & 31;
    const int warp = n >> 5;

    __shared__ __align__(16) unsigned mask[2][16];   // 512-bit spike masks, double buffered

    if (n < 16) mask[0][n] = 0u;

    float* outs  = out;                                        // [B][T][N]
    float* u_all = out + (size_t)BATCH * TT * NN;              // [B][T+1][N]
    float* z_all = u_all + (size_t)BATCH * (TT + 1) * NN;      // [B][T+1][N]

    // t = 0 states are zeros
    u_all[(size_t)b * (TT + 1) * NN + n] = 0.0f;
    z_all[(size_t)b * (TT + 1) * NN + n] = 0.0f;

    const float decay = expf(-DT_F / TAU_F);
    const float omd   = 1.0f - decay;

    const float* curp = g_incur + (size_t)b * TT * NN + n;

    float u = 0.0f;
    float z = 0.0f;
    float cur = __ldg(curp);

    __syncthreads();   // mask[0] visible to all

    for (int t = 0; t < TT; t++) {
        // Prefetch next timestep's feed-forward current
        float cur_next = (t + 1 < TT) ? __ldg(curp + (size_t)(t + 1) * NN) : 0.0f;

        const int p = t & 1;

        // Recurrent input: sum over spiking neurons j of R[n, j] = Rt[j, n]
        float rec = 0.0f;
        uint4 m0 = *(const uint4*)&mask[p][0];
        uint4 m1 = *(const uint4*)&mask[p][4];
        uint4 m2 = *(const uint4*)&mask[p][8];
        uint4 m3 = *(const uint4*)&mask[p][12];
        unsigned mw[16] = {m0.x, m0.y, m0.z, m0.w, m1.x, m1.y, m1.z, m1.w,
                           m2.x, m2.y, m2.z, m2.w, m3.x, m3.y, m3.z, m3.w};
#pragma unroll
        for (int w = 0; w < 16; w++) {
            unsigned bits = mw[w];
            while (bits) {
                int j = (w << 5) + __ffs((int)bits) - 1;
                rec += g_Rt[(size_t)j * NN + n];
                bits &= bits - 1;
            }
        }

        // LIF update (matches reference fp32 math)
        u = u * (1.0f - z);                 // reset with previous spike
        float soma = cur + rec;
        u = decay * u + omd * soma;
        z = (u - THR_F > 0.0f) ? 1.0f : 0.0f;

        // Build next step's spike mask
        unsigned bal = __ballot_sync(0xffffffffu, z != 0.0f);
        if (lane == 0) mask[1 - p][warp] = bal;

        // Emit outputs (fire-and-forget)
        size_t oidx = (size_t)b * TT * NN + (size_t)t * NN + n;
        outs[oidx] = z;
        size_t sidx = (size_t)b * (TT + 1) * NN + (size_t)(t + 1) * NN + n;
        u_all[sidx] = u;
        z_all[sidx] = z;

        cur = cur_next;
        __syncthreads();   // new mask written, old mask done being read
    }
}

// ---------------------------------------------------------------------------
// Launch
// ---------------------------------------------------------------------------
extern "C" void kernel_launch(void* const* d_in, const int* in_sizes, int n_in,
                              void* d_out, int out_size) {
    // Identify inputs robustly by element count
    const float* x = nullptr;   // 64*1000*256 = 16,384,000
    const float* W = nullptr;   // 512*256     = 131,072
    const float* bias = nullptr;// 512
    const float* R = nullptr;   // 512*512     = 262,144
    for (int i = 0; i < n_in; i++) {
        switch (in_sizes[i]) {
            case 16384000: x = (const float*)d_in[i]; break;
            case 131072:   W = (const float*)d_in[i]; break;
            case 512:      bias = (const float*)d_in[i]; break;
            case 262144:   R = (const float*)d_in[i]; break;
            default: break;
        }
    }

    // 1) Transpose R -> Rt
    dim3 tb(32, 32), tg(NN / 32, NN / 32);
    transpose_R_kernel<<<tg, tb>>>(R);

    // 2) Feed-forward GEMM -> g_incur
    dim3 gb(256), gg((BATCH * TT) / 128, NN / 128);
    gemm_kernel<<<gg, gb>>>(x, W, bias);

    // 3) Sequential LIF scan -> d_out
    scan_kernel<<<BATCH, NN>>>((float*)d_out);
}

// round 5
// speedup vs baseline: 1.1634x; 1.1634x over previous
#include <cuda_runtime.h>
#include <cstdint>

// Problem dims (fixed by the dataset)
#define BATCH 64
#define TT    1000
#define DIN   256
#define NN    512

#define THR_F   1.0f
#define TAU_F   20.0f
#define DT_F    1.0f

// Scratch: feed-forward currents [B*T, N] and transposed recurrent matrix
__device__ float g_incur[(size_t)BATCH * TT * NN];   // 131 MB
__device__ float g_Rt[NN * NN];                      // Rt[j*NN + n] = R[n*NN + j]

// ---------------------------------------------------------------------------
// Transpose R (512x512) so the scan can read spike-row contributions coalesced
// ---------------------------------------------------------------------------
__global__ void transpose_R_kernel(const float* __restrict__ R) {
    __shared__ float tile[32][33];
    int x = blockIdx.x * 32 + threadIdx.x;
    int y = blockIdx.y * 32 + threadIdx.y;
    tile[threadIdx.y][threadIdx.x] = R[y * NN + x];
    __syncthreads();
    int xo = blockIdx.y * 32 + threadIdx.x;
    int yo = blockIdx.x * 32 + threadIdx.y;
    g_Rt[yo * NN + xo] = tile[threadIdx.x][threadIdx.y];
}

// ---------------------------------------------------------------------------
// Packed f32x2 FMA helper (2 independent fp32 FMAs per issue slot; FFMA is
// half-rate (rt=2) on sm_10x, FFMA2 restores full fp32 throughput).
// ---------------------------------------------------------------------------
__device__ __forceinline__ void ffma2(unsigned long long& d,
                                      unsigned long long a,
                                      unsigned long long b) {
    asm("fma.rn.f32x2 %0, %1, %2, %0;" : "+l"(d) : "l"(a), "l"(b));
}

// ---------------------------------------------------------------------------
// GEMM: in_cur[m, n] = sum_k x[m,k] * W[n,k] + b[n]
// M = 64000, K = 256, N = 512. Exact fp32 via packed f32x2 FMA.
// 128x128 tile, BK=8, 256 threads, 8x8 per-thread micro-tile (4 f32x2 cols).
// Double-buffered shared memory with register-staged global prefetch.
//   As2: A values DUPLICATED (As2[k][2m] == As2[k][2m+1]) so one LDS.64
//        yields an {a,a} splat pair with no MOV packing.
//   Bs:  normal layout; LDS.128 register pairs are used directly as f32x2.
// ---------------------------------------------------------------------------
__global__ __launch_bounds__(256) void gemm_kernel(const float* __restrict__ A,
                                                   const float* __restrict__ W,
                                                   const float* __restrict__ bias) {
    __shared__ __align__(16) float As2[2][8][256];  // duplicated A, 16 KB
    __shared__ __align__(16) float Bs[2][8][128];   // 8 KB

    const int tid = threadIdx.x;
    const int bm  = blockIdx.x * 128;
    const int bn  = blockIdx.y * 128;

    // Loader mapping: 256 threads, each loads one float4 of the 128x8 tile
    const int lrow = tid >> 1;          // 0..127
    const int lcol = (tid & 1) << 2;    // 0 or 4

    const float* Aptr = A + (size_t)(bm + lrow) * DIN + lcol;
    const float* Wptr = W + (size_t)(bn + lrow) * DIN + lcol;

    // Compute mapping: 16x16 thread grid, 8(m) x 8(n) micro-tile
    const int ty = tid >> 4;
    const int tx = tid & 15;
    const int rm = ty * 8;
    const int rn = tx * 8;

    unsigned long long acc[8][4];
#pragma unroll
    for (int i = 0; i < 8; i++)
#pragma unroll
        for (int j = 0; j < 4; j++) acc[i][j] = 0ull;

    // Prologue: load tile 0
    float4 av = *(const float4*)(Aptr);
    float4 wv = *(const float4*)(Wptr);
    {
        float2 d;
        d.x = av.x; d.y = av.x; *(float2*)&As2[0][lcol + 0][2 * lrow] = d;
        d.x = av.y; d.y = av.y; *(float2*)&As2[0][lcol + 1][2 * lrow] = d;
        d.x = av.z; d.y = av.z; *(float2*)&As2[0][lcol + 2][2 * lrow] = d;
        d.x = av.w; d.y = av.w; *(float2*)&As2[0][lcol + 3][2 * lrow] = d;
        Bs[0][lcol + 0][lrow] = wv.x;
        Bs[0][lcol + 1][lrow] = wv.y;
        Bs[0][lcol + 2][lrow] = wv.z;
        Bs[0][lcol + 3][lrow] = wv.w;
    }
    __syncthreads();

    const int NT = DIN / 8;   // 32 k-tiles
    for (int k0 = 0; k0 < NT; k0++) {
        const int buf = k0 & 1;

        // Prefetch next tile into registers (hide global latency)
        if (k0 + 1 < NT) {
            av = *(const float4*)(Aptr + (k0 + 1) * 8);
            wv = *(const float4*)(Wptr + (k0 + 1) * 8);
        }

#pragma unroll
        for (int k = 0; k < 8; k++) {
            unsigned long long a[8];
#pragma unroll
            for (int i = 0; i < 8; i++)
                a[i] = *(const unsigned long long*)&As2[buf][k][2 * (rm + i)];
            ulonglong2 b01 = *(const ulonglong2*)&Bs[buf][k][rn];
            ulonglong2 b23 = *(const ulonglong2*)&Bs[buf][k][rn + 4];
            unsigned long long b[4] = {b01.x, b01.y, b23.x, b23.y};
#pragma unroll
            for (int i = 0; i < 8; i++)
#pragma unroll
                for (int j = 0; j < 4; j++) ffma2(acc[i][j], a[i], b[j]);
        }

        // Stage next tile into the other buffer
        if (k0 + 1 < NT) {
            const int nb = (k0 + 1) & 1;
            float2 d;
            d.x = av.x; d.y = av.x; *(float2*)&As2[nb][lcol + 0][2 * lrow] = d;
            d.x = av.y; d.y = av.y; *(float2*)&As2[nb][lcol + 1][2 * lrow] = d;
            d.x = av.z; d.y = av.z; *(float2*)&As2[nb][lcol + 2][2 * lrow] = d;
            d.x = av.w; d.y = av.w; *(float2*)&As2[nb][lcol + 3][2 * lrow] = d;
            Bs[nb][lcol + 0][lrow] = wv.x;
            Bs[nb][lcol + 1][lrow] = wv.y;
            Bs[nb][lcol + 2][lrow] = wv.z;
            Bs[nb][lcol + 3][lrow] = wv.w;
        }
        __syncthreads();
    }

    // Epilogue: unpack, add bias, store two float4 per row
    float bv[8];
#pragma unroll
    for (int j = 0; j < 8; j++) bv[j] = __ldg(&bias[bn + rn + j]);

#pragma unroll
    for (int i = 0; i < 8; i++) {
        float c[8];
#pragma unroll
        for (int j = 0; j < 4; j++) {
            unsigned lo, hi;
            asm("mov.b64 {%0, %1}, %2;" : "=r"(lo), "=r"(hi) : "l"(acc[i][j]));
            c[2 * j]     = __uint_as_float(lo) + bv[2 * j];
            c[2 * j + 1] = __uint_as_float(hi) + bv[2 * j + 1];
        }
        size_t row = (size_t)(bm + rm + i) * NN + bn + rn;
        float4 v0 = {c[0], c[1], c[2], c[3]};
        float4 v1 = {c[4], c[5], c[6], c[7]};
        *(float4*)&g_incur[row]     = v0;
        *(float4*)&g_incur[row + 4] = v1;
    }
}

// ---------------------------------------------------------------------------
// Sequential LIF scan. One block per batch element, one thread per neuron.
// __syncthreads_or fuses the step barrier with an "any spike?" reduction:
// when no neuron spiked (the common case), the entire recurrent path —
// mask loads and bit-scan — is skipped. Mask buffer needs no initialization
// because it is only read on steps where ballot just wrote it.
// ---------------------------------------------------------------------------
__global__ __launch_bounds__(NN) void scan_kernel(float* __restrict__ out) {
    const int b = blockIdx.x;
    const int n = threadIdx.x;
    const int lane = n & 31;
    const int warp = n >> 5;

    __shared__ __align__(16) unsigned mask[2][16];   // 512-bit spike masks, double buffered

    float* outs  = out;                                        // [B][T][N]
    float* u_all = out + (size_t)BATCH * TT * NN;              // [B][T+1][N]
    float* z_all = u_all + (size_t)BATCH * (TT + 1) * NN;      // [B][T+1][N]

    // t = 0 states are zeros
    __stcs(&u_all[(size_t)b * (TT + 1) * NN + n], 0.0f);
    __stcs(&z_all[(size_t)b * (TT + 1) * NN + n], 0.0f);

    const float decay = expf(-DT_F / TAU_F);
    const float omd   = 1.0f - decay;

    const float* curp = g_incur + (size_t)b * TT * NN + n;

    float u = 0.0f;
    float z = 0.0f;
    float cur = __ldcs(curp);

    for (int t = 0; t < TT; t++) {
        // Prefetch next timestep's feed-forward current (streaming)
        float cur_next = (t + 1 < TT) ? __ldcs(curp + (size_t)(t + 1) * NN) : 0.0f;

        // Barrier + block-wide "did anyone spike last step?" in one BAR.RED.
        // Also makes last step's mask writes visible.
        const int any = __syncthreads_or(z != 0.0f);

        const int p = t & 1;
        float rec = 0.0f;
        if (any) {
#pragma unroll
            for (int w = 0; w < 16; w++) {
                unsigned bits = mask[p][w];
                while (bits) {
                    int j = (w << 5) + __ffs((int)bits) - 1;
                    rec += g_Rt[(size_t)j * NN + n];
                    bits &= bits - 1;
                }
            }
        }

        // LIF update (matches reference fp32 math)
        u = u * (1.0f - z);                 // reset with previous spike
        float soma = cur + rec;
        u = decay * u + omd * soma;
        z = (u - THR_F > 0.0f) ? 1.0f : 0.0f;

        // Build next step's spike mask
        unsigned bal = __ballot_sync(0xffffffffu, z != 0.0f);
        if (lane == 0) mask[1 - p][warp] = bal;

        // Emit outputs (streaming, fire-and-forget)
        size_t oidx = (size_t)b * TT * NN + (size_t)t * NN + n;
        __stcs(&outs[oidx], z);
        size_t sidx = (size_t)b * (TT + 1) * NN + (size_t)(t + 1) * NN + n;
        __stcs(&u_all[sidx], u);
        __stcs(&z_all[sidx], z);

        cur = cur_next;
    }
}

// ---------------------------------------------------------------------------
// Launch
// ---------------------------------------------------------------------------
extern "C" void kernel_launch(void* const* d_in, const int* in_sizes, int n_in,
                              void* d_out, int out_size) {
    // Identify inputs robustly by element count
    const float* x = nullptr;    // 64*1000*256 = 16,384,000
    const float* W = nullptr;    // 512*256     = 131,072
    const float* bias = nullptr; // 512
    const float* R = nullptr;    // 512*512     = 262,144
    for (int i = 0; i < n_in; i++) {
        switch (in_sizes[i]) {
            case 16384000: x = (const float*)d_in[i]; break;
            case 131072:   W = (const float*)d_in[i]; break;
            case 512:      bias = (const float*)d_in[i]; break;
            case 262144:   R = (const float*)d_in[i]; break;
            default: break;
        }
    }

    // 1) Transpose R -> Rt
    dim3 tb(32, 32), tg(NN / 32, NN / 32);
    transpose_R_kernel<<<tg, tb>>>(R);

    // 2) Feed-forward GEMM -> g_incur
    dim3 gb(256), gg((BATCH * TT) / 128, NN / 128);
    gemm_kernel<<<gg, gb>>>(x, W, bias);

    // 3) Sequential LIF scan -> d_out
    scan_kernel<<<BATCH, NN>>>((float*)d_out);
}

// round 7
// speedup vs baseline: 1.1825x; 1.0164x over previous
#include <cuda_runtime.h>
#include <cstdint>

// Problem dims (fixed by the dataset)
#define BATCH 64
#define TT    1000
#define DIN   256
#define NN    512

#define THR_F   1.0f
#define TAU_F   20.0f
#define DT_F    1.0f

// Scratch: feed-forward currents [B*T, N], transposed recurrent matrix,
// and per-batch "speculation failed" flags.
__device__ float g_incur[(size_t)BATCH * TT * NN];   // 131 MB
__device__ float g_Rt[NN * NN];                      // Rt[j*NN + n] = R[n*NN + j]
__device__ int   g_flag[BATCH];                      // 1 => batch b had a spike

// ---------------------------------------------------------------------------
// Transpose R (512x512) + clear speculation flags (runs first each launch)
// ---------------------------------------------------------------------------
__global__ void transpose_R_kernel(const float* __restrict__ R) {
    __shared__ float tile[32][33];
    if (blockIdx.x == 0 && blockIdx.y == 0) {
        int lin = threadIdx.y * 32 + threadIdx.x;
        if (lin < BATCH) g_flag[lin] = 0;
    }
    int x = blockIdx.x * 32 + threadIdx.x;
    int y = blockIdx.y * 32 + threadIdx.y;
    tile[threadIdx.y][threadIdx.x] = R[y * NN + x];
    __syncthreads();
    int xo = blockIdx.y * 32 + threadIdx.x;
    int yo = blockIdx.x * 32 + threadIdx.y;
    g_Rt[yo * NN + xo] = tile[threadIdx.x][threadIdx.y];
}

// ---------------------------------------------------------------------------
// Packed f32x2 FMA helper (2 independent fp32 FMAs per issue slot; FFMA is
// half-rate (rt=2) on sm_10x, FFMA2 restores full fp32 throughput).
// ---------------------------------------------------------------------------
__device__ __forceinline__ void ffma2(unsigned long long& d,
                                      unsigned long long a,
                                      unsigned long long b) {
    asm("fma.rn.f32x2 %0, %1, %2, %0;" : "+l"(d) : "l"(a), "l"(b));
}

// ---------------------------------------------------------------------------
// GEMM: in_cur[m, n] = sum_k x[m,k] * W[n,k] + b[n]   (frozen from R5)
// M = 64000, K = 256, N = 512. Exact fp32 via packed f32x2 FMA.
// ---------------------------------------------------------------------------
__global__ __launch_bounds__(256) void gemm_kernel(const float* __restrict__ A,
                                                   const float* __restrict__ W,
                                                   const float* __restrict__ bias) {
    __shared__ __align__(16) float As2[2][8][256];  // duplicated A, 16 KB
    __shared__ __align__(16) float Bs[2][8][128];   // 8 KB

    const int tid = threadIdx.x;
    const int bm  = blockIdx.x * 128;
    const int bn  = blockIdx.y * 128;

    const int lrow = tid >> 1;          // 0..127
    const int lcol = (tid & 1) << 2;    // 0 or 4

    const float* Aptr = A + (size_t)(bm + lrow) * DIN + lcol;
    const float* Wptr = W + (size_t)(bn + lrow) * DIN + lcol;

    const int ty = tid >> 4;
    const int tx = tid & 15;
    const int rm = ty * 8;
    const int rn = tx * 8;

    unsigned long long acc[8][4];
#pragma unroll
    for (int i = 0; i < 8; i++)
#pragma unroll
        for (int j = 0; j < 4; j++) acc[i][j] = 0ull;

    float4 av = *(const float4*)(Aptr);
    float4 wv = *(const float4*)(Wptr);
    {
        float2 d;
        d.x = av.x; d.y = av.x; *(float2*)&As2[0][lcol + 0][2 * lrow] = d;
        d.x = av.y; d.y = av.y; *(float2*)&As2[0][lcol + 1][2 * lrow] = d;
        d.x = av.z; d.y = av.z; *(float2*)&As2[0][lcol + 2][2 * lrow] = d;
        d.x = av.w; d.y = av.w; *(float2*)&As2[0][lcol + 3][2 * lrow] = d;
        Bs[0][lcol + 0][lrow] = wv.x;
        Bs[0][lcol + 1][lrow] = wv.y;
        Bs[0][lcol + 2][lrow] = wv.z;
        Bs[0][lcol + 3][lrow] = wv.w;
    }
    __syncthreads();

    const int NT = DIN / 8;   // 32 k-tiles
    for (int k0 = 0; k0 < NT; k0++) {
        const int buf = k0 & 1;

        if (k0 + 1 < NT) {
            av = *(const float4*)(Aptr + (k0 + 1) * 8);
            wv = *(const float4*)(Wptr + (k0 + 1) * 8);
        }

#pragma unroll
        for (int k = 0; k < 8; k++) {
            unsigned long long a[8];
#pragma unroll
            for (int i = 0; i < 8; i++)
                a[i] = *(const unsigned long long*)&As2[buf][k][2 * (rm + i)];
            ulonglong2 b01 = *(const ulonglong2*)&Bs[buf][k][rn];
            ulonglong2 b23 = *(const ulonglong2*)&Bs[buf][k][rn + 4];
            unsigned long long b[4] = {b01.x, b01.y, b23.x, b23.y};
#pragma unroll
            for (int i = 0; i < 8; i++)
#pragma unroll
                for (int j = 0; j < 4; j++) ffma2(acc[i][j], a[i], b[j]);
        }

        if (k0 + 1 < NT) {
            const int nb = (k0 + 1) & 1;
            float2 d;
            d.x = av.x; d.y = av.x; *(float2*)&As2[nb][lcol + 0][2 * lrow] = d;
            d.x = av.y; d.y = av.y; *(float2*)&As2[nb][lcol + 1][2 * lrow] = d;
            d.x = av.z; d.y = av.z; *(float2*)&As2[nb][lcol + 2][2 * lrow] = d;
            d.x = av.w; d.y = av.w; *(float2*)&As2[nb][lcol + 3][2 * lrow] = d;
            Bs[nb][lcol + 0][lrow] = wv.x;
            Bs[nb][lcol + 1][lrow] = wv.y;
            Bs[nb][lcol + 2][lrow] = wv.z;
            Bs[nb][lcol + 3][lrow] = wv.w;
        }
        __syncthreads();
    }

    float bv[8];
#pragma unroll
    for (int j = 0; j < 8; j++) bv[j] = __ldg(&bias[bn + rn + j]);

#pragma unroll
    for (int i = 0; i < 8; i++) {
        float c[8];
#pragma unroll
        for (int j = 0; j < 4; j++) {
            unsigned lo, hi;
            asm("mov.b64 {%0, %1}, %2;" : "=r"(lo), "=r"(hi) : "l"(acc[i][j]));
            c[2 * j]     = __uint_as_float(lo) + bv[2 * j];
            c[2 * j + 1] = __uint_as_float(hi) + bv[2 * j + 1];
        }
        size_t row = (size_t)(bm + rm + i) * NN + bn + rn;
        float4 v0 = {c[0], c[1], c[2], c[3]};
        float4 v1 = {c[4], c[5], c[6], c[7]};
        *(float4*)&g_incur[row]     = v0;
        *(float4*)&g_incur[row + 4] = v1;
    }
}

// ---------------------------------------------------------------------------
// SPECULATIVE scan: assumes zero spikes (true for this data: u ~ 11 sigma
// below threshold). With z == 0 the recurrence decouples per neuron:
//     u_t = decay * u_{t-1} + omd * cur_t        (bit-identical expression
// to the sequential kernel, full sequence per thread => rel_err unchanged).
// One thread handles 2 adjacent neurons; no barriers, no shared memory —
// pure streaming (524 MB) instead of 1000 serialized block barriers.
// The FIRST threshold crossing is always detected exactly (a spike only
// alters strictly-later timesteps), so any spike => g_flag[b] = 1 and the
// exact fallback kernel redoes that batch.
// ---------------------------------------------------------------------------
__global__ __launch_bounds__(128) void spec_scan_kernel(float* __restrict__ out) {
    const int idx = blockIdx.x * 128 + threadIdx.x;   // 0..16383
    const int b   = idx >> 8;                         // 256 neuron-pairs per batch
    const int n2  = (idx & 255) << 1;                 // even neuron index

    float* outs  = out;                                        // [B][T][N]
    float* u_all = out + (size_t)BATCH * TT * NN;              // [B][T+1][N]
    float* z_all = u_all + (size_t)BATCH * (TT + 1) * NN;      // [B][T+1][N]

    const size_t ub = (size_t)b * (TT + 1) * NN + n2;
    const size_t ob = (size_t)b * TT * NN + n2;

    // t = 0 states are zeros
    float2 zz; zz.x = 0.0f; zz.y = 0.0f;
    __stcs((float2*)&u_all[ub], zz);
    __stcs((float2*)&z_all[ub], zz);

    const float decay = expf(-DT_F / TAU_F);
    const float omd   = 1.0f - decay;

    const float* curp = g_incur + (size_t)b * TT * NN + n2;

    float u0 = 0.0f, u1 = 0.0f;
    bool spiked = false;

#pragma unroll 4
    for (int t = 0; t < TT; t++) {
        float2 c = __ldcs((const float2*)(curp + (size_t)t * NN));

        // identical fp32 math to the exact kernel with z = 0, rec = 0
        u0 = decay * u0 + omd * c.x;
        u1 = decay * u1 + omd * c.y;
        float z0 = (u0 - THR_F > 0.0f) ? 1.0f : 0.0f;
        float z1 = (u1 - THR_F > 0.0f) ? 1.0f : 0.0f;
        spiked = spiked || (z0 != 0.0f) || (z1 != 0.0f);

        float2 zv; zv.x = z0; zv.y = z1;
        float2 uv; uv.x = u0; uv.y = u1;
        __stcs((float2*)&outs[ob + (size_t)t * NN], zv);
        __stcs((float2*)&u_all[ub + (size_t)(t + 1) * NN], uv);
        __stcs((float2*)&z_all[ub + (size_t)(t + 1) * NN], zv);
    }

    if (spiked) g_flag[b] = 1;
}

// ---------------------------------------------------------------------------
// EXACT fallback scan (the proven R5 kernel), gated per batch: runs only if
// speculation detected a spike in this batch. No-op (~us) on clean input;
// fully correct (reset + recurrent term) otherwise.
// ---------------------------------------------------------------------------
__global__ __launch_bounds__(NN) void fallback_scan_kernel(float* __restrict__ out) {
    const int b = blockIdx.x;
    if (g_flag[b] == 0) return;            // speculation held for this batch

    const int n = threadIdx.x;
    const int lane = n & 31;
    const int warp = n >> 5;

    __shared__ __align__(16) unsigned mask[2][16];

    float* outs  = out;
    float* u_all = out + (size_t)BATCH * TT * NN;
    float* z_all = u_all + (size_t)BATCH * (TT + 1) * NN;

    __stcs(&u_all[(size_t)b * (TT + 1) * NN + n], 0.0f);
    __stcs(&z_all[(size_t)b * (TT + 1) * NN + n], 0.0f);

    const float decay = expf(-DT_F / TAU_F);
    const float omd   = 1.0f - decay;

    const float* curp = g_incur + (size_t)b * TT * NN + n;

    float u = 0.0f;
    float z = 0.0f;
    float cur = __ldcs(curp);

    for (int t = 0; t < TT; t++) {
        float cur_next = (t + 1 < TT) ? __ldcs(curp + (size_t)(t + 1) * NN) : 0.0f;

        const int any = __syncthreads_or(z != 0.0f);

        const int p = t & 1;
        float rec = 0.0f;
        if (any) {
#pragma unroll
            for (int w = 0; w < 16; w++) {
                unsigned bits = mask[p][w];
                while (bits) {
                    int j = (w << 5) + __ffs((int)bits) - 1;
                    rec += g_Rt[(size_t)j * NN + n];
                    bits &= bits - 1;
                }
            }
        }

        u = u * (1.0f - z);
        float soma = cur + rec;
        u = decay * u + omd * soma;
        z = (u - THR_F > 0.0f) ? 1.0f : 0.0f;

        unsigned bal = __ballot_sync(0xffffffffu, z != 0.0f);
        if (lane == 0) mask[1 - p][warp] = bal;

        size_t oidx = (size_t)b * TT * NN + (size_t)t * NN + n;
        __stcs(&outs[oidx], z);
        size_t sidx = (size_t)b * (TT + 1) * NN + (size_t)(t + 1) * NN + n;
        __stcs(&u_all[sidx], u);
        __stcs(&z_all[sidx], z);

        cur = cur_next;
    }
}

// ---------------------------------------------------------------------------
// Launch
// ---------------------------------------------------------------------------
extern "C" void kernel_launch(void* const* d_in, const int* in_sizes, int n_in,
                              void* d_out, int out_size) {
    const float* x = nullptr;    // 64*1000*256 = 16,384,000
    const float* W = nullptr;    // 512*256     = 131,072
    const float* bias = nullptr; // 512
    const float* R = nullptr;    // 512*512     = 262,144
    for (int i = 0; i < n_in; i++) {
        switch (in_sizes[i]) {
            case 16384000: x = (const float*)d_in[i]; break;
            case 131072:   W = (const float*)d_in[i]; break;
            case 512:      bias = (const float*)d_in[i]; break;
            case 262144:   R = (const float*)d_in[i]; break;
            default: break;
        }
    }

    // 1) Transpose R -> Rt and clear speculation flags
    dim3 tb(32, 32), tg(NN / 32, NN / 32);
    transpose_R_kernel<<<tg, tb>>>(R);

    // 2) Feed-forward GEMM -> g_incur
    dim3 gb(256), gg((BATCH * TT) / 128, NN / 128);
    gemm_kernel<<<gg, gb>>>(x, W, bias);

    // 3) Speculative barrier-free scan -> d_out (+ per-batch spike flags)
    spec_scan_kernel<<<128, 128>>>((float*)d_out);

    // 4) Exact fallback, gated per batch (no-op when speculation held)
    fallback_scan_kernel<<<BATCH, NN>>>((float*)d_out);
}

// round 11
// speedup vs baseline: 1.7236x; 1.4576x over previous
#include <cuda_runtime.h>
#include <cuda_bf16.h>
#include <cstdint>

// Problem dims (fixed by the dataset)
#define BATCH 64
#define TT    1000
#define DIN   256
#define NN    512

#define THR_F   1.0f
#define TAU_F   20.0f
#define DT_F    1.0f

#define XELEMS  ((size_t)BATCH * TT * DIN)   // 16,384,000
#define MROWS   (BATCH * TT)                 // 64,000

// Scratch
__device__ float          g_incur[(size_t)BATCH * TT * NN];  // 131 MB
__device__ float          g_Rt[NN * NN];
__device__ int            g_flag[BATCH];
__device__ __nv_bfloat16  g_xhi[XELEMS];
__device__ __nv_bfloat16  g_xlo[XELEMS];
__device__ __nv_bfloat16  g_whi[NN * DIN];
__device__ __nv_bfloat16  g_wlo[NN * DIN];

// ===========================================================================
// Transpose R + clear flags (unchanged, proven)
// ===========================================================================
__global__ void transpose_R_kernel(const float* __restrict__ R) {
    __shared__ float tile[32][33];
    if (blockIdx.x == 0 && blockIdx.y == 0) {
        int lin = threadIdx.y * 32 + threadIdx.x;
        if (lin < BATCH) g_flag[lin] = 0;
    }
    int x = blockIdx.x * 32 + threadIdx.x;
    int y = blockIdx.y * 32 + threadIdx.y;
    tile[threadIdx.y][threadIdx.x] = R[y * NN + x];
    __syncthreads();
    int xo = blockIdx.y * 32 + threadIdx.x;
    int yo = blockIdx.x * 32 + threadIdx.y;
    g_Rt[yo * NN + xo] = tile[threadIdx.x][threadIdx.y];
}

// ===========================================================================
// Split fp32 -> (bf16 hi, bf16 lo) for x and W. lo = bf16(v - float(hi)).
// Combined mantissa ~16-17 bits => 3-term product error ~2^-16 << 1e-3.
// ===========================================================================
__global__ __launch_bounds__(256) void split_kernel(const float* __restrict__ x,
                                                    const float* __restrict__ W) {
    size_t i = (size_t)blockIdx.x * 256 + threadIdx.x;
    const size_t XQ = XELEMS / 4;            // 4,096,000
    const size_t WQ = (size_t)NN * DIN / 4;  // 32,768
    const float* src;
    __nv_bfloat16 *dhi, *dlo;
    size_t q;
    if (i < XQ)           { src = x; dhi = g_xhi; dlo = g_xlo; q = i; }
    else if (i < XQ + WQ) { src = W; dhi = g_whi; dlo = g_wlo; q = i - XQ; }
    else return;

    float4 v = *(const float4*)(src + q * 4);
    __nv_bfloat16 h0 = __float2bfloat16(v.x);
    __nv_bfloat16 h1 = __float2bfloat16(v.y);
    __nv_bfloat16 h2 = __float2bfloat16(v.z);
    __nv_bfloat16 h3 = __float2bfloat16(v.w);
    ushort4 hv = { __bfloat16_as_ushort(h0), __bfloat16_as_ushort(h1),
                   __bfloat16_as_ushort(h2), __bfloat16_as_ushort(h3) };
    ushort4 lv = {
        __bfloat16_as_ushort(__float2bfloat16(v.x - __bfloat162float(h0))),
        __bfloat16_as_ushort(__float2bfloat16(v.y - __bfloat162float(h1))),
        __bfloat16_as_ushort(__float2bfloat16(v.z - __bfloat162float(h2))),
        __bfloat16_as_ushort(__float2bfloat16(v.w - __bfloat162float(h3))) };
    *(ushort4*)(dhi + q * 4) = hv;
    *(ushort4*)(dlo + q * 4) = lv;
}

// ===========================================================================
// HMMA GEMM: in_cur = x @ W^T + b via 3 bf16 mma.sync passes (hh + hl + lh)
// with fp32 accumulation. mma.sync.m16n8k16 is arch-generic (sm_80+), so it
// survives the harness's compute_100 PTX stage (tcgen05 does NOT).
//
// Block tile 128(M) x 128(N), 8 warps in 2x4 layout, warp tile 64x32.
// K staged in chunks of 64; 4 smem tiles (A hi/lo 128x64, B hi/lo 128x64)
// with padded stride 72 bf16 -> conflict-free fragment loads
// (bank = (36*row + klane) % 32 covers all 32 banks within a warp).
// W is [N, K] row-major = col-major B with leading dim K: exactly what
// mma.sync row.col wants.
// ===========================================================================
#define BK       64
#define ASTRIDE  72                          // bf16 elements per padded row
#define TILE_BF  (128 * ASTRIDE)             // 9216 bf16 = 18432 B
#define SM_AH    0
#define SM_AL    (TILE_BF)
#define SM_BH    (2 * TILE_BF)
#define SM_BL    (3 * TILE_BF)
#define HMMA_SMEM (4 * TILE_BF * 2)          // 73728 B

__device__ __forceinline__ void mma16816(float* c, const uint32_t* a, const uint32_t* b) {
    asm volatile(
        "mma.sync.aligned.m16n8k16.row.col.f32.bf16.bf16.f32 "
        "{%0,%1,%2,%3}, {%4,%5,%6,%7}, {%8,%9}, {%0,%1,%2,%3};"
        : "+f"(c[0]), "+f"(c[1]), "+f"(c[2]), "+f"(c[3])
        : "r"(a[0]), "r"(a[1]), "r"(a[2]), "r"(a[3]), "r"(b[0]), "r"(b[1]));
}

__global__ __launch_bounds__(256, 2) void gemm_hmma_kernel(const float* __restrict__ bias) {
    extern __shared__ __align__(16) __nv_bfloat16 sm[];

    const int tid    = threadIdx.x;
    const int wid    = tid >> 5;
    const int lane   = tid & 31;
    const int warp_m = wid >> 2;              // 0..1
    const int warp_n = wid & 3;               // 0..3
    const int bm     = blockIdx.x * 128;
    const int bn     = blockIdx.y * 128;

    const int lr = lane >> 2;                 // 0..7  (row-in-8 / n-in-8)
    const int lc = lane & 3;                  // 0..3  (k pair index)

    float acc[4][4][4];                       // [mfrag][nfrag][4]
#pragma unroll
    for (int i = 0; i < 4; i++)
#pragma unroll
        for (int j = 0; j < 4; j++)
#pragma unroll
            for (int e = 0; e < 4; e++) acc[i][j][e] = 0.0f;

    for (int kc = 0; kc < DIN / BK; kc++) {
        // ---- Stage chunk: 4 tiles of 128 rows x 64 k (hi/lo for A and B).
        // 1024 uint4 groups (8 bf16) per tile; 256 threads x 4 iters.
        for (int g = tid; g < 1024; g += 256) {
            int row = g >> 3;
            int kk  = (g & 7) << 3;
            int so  = row * ASTRIDE + kk;
            size_t sa = (size_t)(bm + row) * DIN + (size_t)(kc * BK + kk);
            size_t sb = (size_t)(bn + row) * DIN + (size_t)(kc * BK + kk);
            *(uint4*)(sm + SM_AH + so) = *(const uint4*)(g_xhi + sa);
            *(uint4*)(sm + SM_AL + so) = *(const uint4*)(g_xlo + sa);
            *(uint4*)(sm + SM_BH + so) = *(const uint4*)(g_whi + sb);
            *(uint4*)(sm + SM_BL + so) = *(const uint4*)(g_wlo + sb);
        }
        __syncthreads();

#pragma unroll
        for (int ks = 0; ks < BK / 16; ks++) {
            const int kb = ks * 16 + lc * 2;  // bf16 index of this lane's k pair

            // A fragments (hi and lo) for 4 m-frags of the 64-row warp tile
            uint32_t ah[4][4], al[4][4];
#pragma unroll
            for (int i = 0; i < 4; i++) {
                int r0 = warp_m * 64 + i * 16 + lr;
                const __nv_bfloat16* pa0 = sm + (size_t)r0 * ASTRIDE + kb;
                const __nv_bfloat16* pa1 = sm + (size_t)(r0 + 8) * ASTRIDE + kb;
                ah[i][0] = *(const uint32_t*)(pa0 + SM_AH);
                ah[i][1] = *(const uint32_t*)(pa1 + SM_AH);
                ah[i][2] = *(const uint32_t*)(pa0 + SM_AH + 8);
                ah[i][3] = *(const uint32_t*)(pa1 + SM_AH + 8);
                al[i][0] = *(const uint32_t*)(pa0 + SM_AL);
                al[i][1] = *(const uint32_t*)(pa1 + SM_AL);
                al[i][2] = *(const uint32_t*)(pa0 + SM_AL + 8);
                al[i][3] = *(const uint32_t*)(pa1 + SM_AL + 8);
            }
            // B fragments (hi and lo) for 4 n-frags of the 32-col warp tile
            uint32_t bh[4][2], bl[4][2];
#pragma unroll
            for (int j = 0; j < 4; j++) {
                int n0 = warp_n * 32 + j * 8 + lr;
                const __nv_bfloat16* pb = sm + (size_t)n0 * ASTRIDE + kb;
                bh[j][0] = *(const uint32_t*)(pb + SM_BH);
                bh[j][1] = *(const uint32_t*)(pb + SM_BH + 8);
                bl[j][0] = *(const uint32_t*)(pb + SM_BL);
                bl[j][1] = *(const uint32_t*)(pb + SM_BL + 8);
            }

            // 3-term accumulate: hh + hl + lh
#pragma unroll
            for (int i = 0; i < 4; i++)
#pragma unroll
                for (int j = 0; j < 4; j++) {
                    mma16816(acc[i][j], ah[i], bh[j]);
                    mma16816(acc[i][j], ah[i], bl[j]);
                    mma16816(acc[i][j], al[i], bh[j]);
                }
        }
        __syncthreads();
    }

    // ---- Epilogue: add bias, store float2 pairs
#pragma unroll
    for (int j = 0; j < 4; j++) {
        int col = bn + warp_n * 32 + j * 8 + lc * 2;
        float b0 = __ldg(&bias[col]);
        float b1 = __ldg(&bias[col + 1]);
#pragma unroll
        for (int i = 0; i < 4; i++) {
            int r0 = bm + warp_m * 64 + i * 16 + lr;
            float2 v0 = { acc[i][j][0] + b0, acc[i][j][1] + b1 };
            float2 v1 = { acc[i][j][2] + b0, acc[i][j][3] + b1 };
            *(float2*)&g_incur[(size_t)r0 * NN + col]       = v0;
            *(float2*)&g_incur[(size_t)(r0 + 8) * NN + col] = v1;
        }
    }
}

// ===========================================================================
// Speculative barrier-free scan (unchanged, proven in R7)
// ===========================================================================
__global__ __launch_bounds__(128) void spec_scan_kernel(float* __restrict__ out) {
    const int idx = blockIdx.x * 128 + threadIdx.x;
    const int b   = idx >> 8;
    const int n2  = (idx & 255) << 1;

    float* outs  = out;
    float* u_all = out + (size_t)BATCH * TT * NN;
    float* z_all = u_all + (size_t)BATCH * (TT + 1) * NN;

    const size_t ub = (size_t)b * (TT + 1) * NN + n2;
    const size_t ob = (size_t)b * TT * NN + n2;

    float2 zz; zz.x = 0.0f; zz.y = 0.0f;
    __stcs((float2*)&u_all[ub], zz);
    __stcs((float2*)&z_all[ub], zz);

    const float decay = expf(-DT_F / TAU_F);
    const float omd   = 1.0f - decay;

    const float* curp = g_incur + (size_t)b * TT * NN + n2;

    float u0 = 0.0f, u1 = 0.0f;
    bool spiked = false;

#pragma unroll 4
    for (int t = 0; t < TT; t++) {
        float2 c = __ldcs((const float2*)(curp + (size_t)t * NN));
        u0 = decay * u0 + omd * c.x;
        u1 = decay * u1 + omd * c.y;
        float z0 = (u0 - THR_F > 0.0f) ? 1.0f : 0.0f;
        float z1 = (u1 - THR_F > 0.0f) ? 1.0f : 0.0f;
        spiked = spiked || (z0 != 0.0f) || (z1 != 0.0f);

        float2 zv; zv.x = z0; zv.y = z1;
        float2 uv; uv.x = u0; uv.y = u1;
        __stcs((float2*)&outs[ob + (size_t)t * NN], zv);
        __stcs((float2*)&u_all[ub + (size_t)(t + 1) * NN], uv);
        __stcs((float2*)&z_all[ub + (size_t)(t + 1) * NN], zv);
    }

    if (spiked) g_flag[b] = 1;
}

// ===========================================================================
// Exact fallback scan, gated per batch (unchanged, proven)
// ===========================================================================
__global__ __launch_bounds__(NN) void fallback_scan_kernel(float* __restrict__ out) {
    const int b = blockIdx.x;
    if (g_flag[b] == 0) return;

    const int n = threadIdx.x;
    const int lane = n & 31;
    const int warp = n >> 5;

    __shared__ __align__(16) unsigned mask[2][16];

    float* outs  = out;
    float* u_all = out + (size_t)BATCH * TT * NN;
    float* z_all = u_all + (size_t)BATCH * (TT + 1) * NN;

    __stcs(&u_all[(size_t)b * (TT + 1) * NN + n], 0.0f);
    __stcs(&z_all[(size_t)b * (TT + 1) * NN + n], 0.0f);

    const float decay = expf(-DT_F / TAU_F);
    const float omd   = 1.0f - decay;

    const float* curp = g_incur + (size_t)b * TT * NN + n;

    float u = 0.0f;
    float z = 0.0f;
    float cur = __ldcs(curp);

    for (int t = 0; t < TT; t++) {
        float cur_next = (t + 1 < TT) ? __ldcs(curp + (size_t)(t + 1) * NN) : 0.0f;

        const int any = __syncthreads_or(z != 0.0f);

        const int p = t & 1;
        float rec = 0.0f;
        if (any) {
#pragma unroll
            for (int w = 0; w < 16; w++) {
                unsigned bits = mask[p][w];
                while (bits) {
                    int j = (w << 5) + __ffs((int)bits) - 1;
                    rec += g_Rt[(size_t)j * NN + n];
                    bits &= bits - 1;
                }
            }
        }

        u = u * (1.0f - z);
        float soma = cur + rec;
        u = decay * u + omd * soma;
        z = (u - THR_F > 0.0f) ? 1.0f : 0.0f;

        unsigned bal = __ballot_sync(0xffffffffu, z != 0.0f);
        if (lane == 0) mask[1 - p][warp] = bal;

        size_t oidx = (size_t)b * TT * NN + (size_t)t * NN + n;
        __stcs(&outs[oidx], z);
        size_t sidx = (size_t)b * (TT + 1) * NN + (size_t)(t + 1) * NN + n;
        __stcs(&u_all[sidx], u);
        __stcs(&z_all[sidx], z);

        cur = cur_next;
    }
}

// ===========================================================================
// Launch
// ===========================================================================
extern "C" void kernel_launch(void* const* d_in, const int* in_sizes, int n_in,
                              void* d_out, int out_size) {
    const float* x = nullptr;    // 16,384,000
    const float* W = nullptr;    // 131,072
    const float* bias = nullptr; // 512
    const float* R = nullptr;    // 262,144
    for (int i = 0; i < n_in; i++) {
        switch (in_sizes[i]) {
            case 16384000: x = (const float*)d_in[i]; break;
            case 131072:   W = (const float*)d_in[i]; break;
            case 512:      bias = (const float*)d_in[i]; break;
            case 262144:   R = (const float*)d_in[i]; break;
            default: break;
        }
    }

    // 72 KB dynamic smem for the HMMA GEMM (idempotent attribute set, no alloc)
    cudaFuncSetAttribute(gemm_hmma_kernel,
                         cudaFuncAttributeMaxDynamicSharedMemorySize, HMMA_SMEM);

    // 1) Transpose R -> Rt and clear speculation flags
    dim3 tb(32, 32), tg(NN / 32, NN / 32);
    transpose_R_kernel<<<tg, tb>>>(R);

    // 2) Split x, W into bf16 hi/lo pairs
    split_kernel<<<16128, 256>>>(x, W);

    // 3) HMMA GEMM (3x bf16 mma.sync, fp32 accum) -> g_incur
    gemm_hmma_kernel<<<dim3(MROWS / 128, NN / 128), 256, HMMA_SMEM>>>(bias);

    // 4) Speculative barrier-free scan -> d_out (+ per-batch spike flags)
    spec_scan_kernel<<<128, 128>>>((float*)d_out);

    // 5) Exact fallback, gated per batch (no-op when speculation held)
    fallback_scan_kernel<<<BATCH, NN>>>((float*)d_out);
}

// round 13
// speedup vs baseline: 3.5837x; 2.0793x over previous
#include <cuda_runtime.h>
#include <cuda_bf16.h>
#include <cstdint>

// Problem dims (fixed by the dataset)
#define BATCH 64
#define TT    1000
#define DIN   256
#define NN    512

#define THR_F   1.0f
#define TAU_F   20.0f
#define DT_F    1.0f

// Time chunking for the scan: 20 chunks x 50 steps
#define NCHUNK  20
#define CLEN    50

#define XELEMS  ((size_t)BATCH * TT * DIN)   // 16,384,000
#define MROWS   (BATCH * TT)                 // 64,000

// Scratch
__device__ float          g_incur[(size_t)BATCH * TT * NN];  // 131 MB
__device__ float          g_Rt[NN * NN];
__device__ int            g_flag[BATCH];
__device__ __nv_bfloat16  g_xhi[XELEMS];
__device__ __nv_bfloat16  g_xlo[XELEMS];
__device__ __nv_bfloat16  g_whi[NN * DIN];
__device__ __nv_bfloat16  g_wlo[NN * DIN];
__device__ float          g_uend[NCHUNK * BATCH * NN];       // chunk-local end states
__device__ float          g_uin [NCHUNK * BATCH * NN];       // chunk entry states

// ===========================================================================
// Transpose R + clear flags (unchanged, proven)
// ===========================================================================
__global__ void transpose_R_kernel(const float* __restrict__ R) {
    __shared__ float tile[32][33];
    if (blockIdx.x == 0 && blockIdx.y == 0) {
        int lin = threadIdx.y * 32 + threadIdx.x;
        if (lin < BATCH) g_flag[lin] = 0;
    }
    int x = blockIdx.x * 32 + threadIdx.x;
    int y = blockIdx.y * 32 + threadIdx.y;
    tile[threadIdx.y][threadIdx.x] = R[y * NN + x];
    __syncthreads();
    int xo = blockIdx.y * 32 + threadIdx.x;
    int yo = blockIdx.x * 32 + threadIdx.y;
    g_Rt[yo * NN + xo] = tile[threadIdx.x][threadIdx.y];
}

// ===========================================================================
// Split fp32 -> (bf16 hi, bf16 lo) for x and W (unchanged, proven)
// ===========================================================================
__global__ __launch_bounds__(256) void split_kernel(const float* __restrict__ x,
                                                    const float* __restrict__ W) {
    size_t i = (size_t)blockIdx.x * 256 + threadIdx.x;
    const size_t XQ = XELEMS / 4;
    const size_t WQ = (size_t)NN * DIN / 4;
    const float* src;
    __nv_bfloat16 *dhi, *dlo;
    size_t q;
    if (i < XQ)           { src = x; dhi = g_xhi; dlo = g_xlo; q = i; }
    else if (i < XQ + WQ) { src = W; dhi = g_whi; dlo = g_wlo; q = i - XQ; }
    else return;

    float4 v = *(const float4*)(src + q * 4);
    __nv_bfloat16 h0 = __float2bfloat16(v.x);
    __nv_bfloat16 h1 = __float2bfloat16(v.y);
    __nv_bfloat16 h2 = __float2bfloat16(v.z);
    __nv_bfloat16 h3 = __float2bfloat16(v.w);
    ushort4 hv = { __bfloat16_as_ushort(h0), __bfloat16_as_ushort(h1),
                   __bfloat16_as_ushort(h2), __bfloat16_as_ushort(h3) };
    ushort4 lv = {
        __bfloat16_as_ushort(__float2bfloat16(v.x - __bfloat162float(h0))),
        __bfloat16_as_ushort(__float2bfloat16(v.y - __bfloat162float(h1))),
        __bfloat16_as_ushort(__float2bfloat16(v.z - __bfloat162float(h2))),
        __bfloat16_as_ushort(__float2bfloat16(v.w - __bfloat162float(h3))) };
    *(ushort4*)(dhi + q * 4) = hv;
    *(ushort4*)(dlo + q * 4) = lv;
}

// ===========================================================================
// HMMA GEMM (unchanged, proven in R11: ~170us)
// ===========================================================================
#define BK       64
#define ASTRIDE  72
#define TILE_BF  (128 * ASTRIDE)
#define SM_AH    0
#define SM_AL    (TILE_BF)
#define SM_BH    (2 * TILE_BF)
#define SM_BL    (3 * TILE_BF)
#define HMMA_SMEM (4 * TILE_BF * 2)          // 73728 B

__device__ __forceinline__ void mma16816(float* c, const uint32_t* a, const uint32_t* b) {
    asm volatile(
        "mma.sync.aligned.m16n8k16.row.col.f32.bf16.bf16.f32 "
        "{%0,%1,%2,%3}, {%4,%5,%6,%7}, {%8,%9}, {%0,%1,%2,%3};"
        : "+f"(c[0]), "+f"(c[1]), "+f"(c[2]), "+f"(c[3])
        : "r"(a[0]), "r"(a[1]), "r"(a[2]), "r"(a[3]), "r"(b[0]), "r"(b[1]));
}

__global__ __launch_bounds__(256, 2) void gemm_hmma_kernel(const float* __restrict__ bias) {
    extern __shared__ __align__(16) __nv_bfloat16 sm[];

    const int tid    = threadIdx.x;
    const int wid    = tid >> 5;
    const int lane   = tid & 31;
    const int warp_m = wid >> 2;
    const int warp_n = wid & 3;
    const int bm     = blockIdx.x * 128;
    const int bn     = blockIdx.y * 128;

    const int lr = lane >> 2;
    const int lc = lane & 3;

    float acc[4][4][4];
#pragma unroll
    for (int i = 0; i < 4; i++)
#pragma unroll
        for (int j = 0; j < 4; j++)
#pragma unroll
            for (int e = 0; e < 4; e++) acc[i][j][e] = 0.0f;

    for (int kc = 0; kc < DIN / BK; kc++) {
        for (int g = tid; g < 1024; g += 256) {
            int row = g >> 3;
            int kk  = (g & 7) << 3;
            int so  = row * ASTRIDE + kk;
            size_t sa = (size_t)(bm + row) * DIN + (size_t)(kc * BK + kk);
            size_t sb = (size_t)(bn + row) * DIN + (size_t)(kc * BK + kk);
            *(uint4*)(sm + SM_AH + so) = *(const uint4*)(g_xhi + sa);
            *(uint4*)(sm + SM_AL + so) = *(const uint4*)(g_xlo + sa);
            *(uint4*)(sm + SM_BH + so) = *(const uint4*)(g_whi + sb);
            *(uint4*)(sm + SM_BL + so) = *(const uint4*)(g_wlo + sb);
        }
        __syncthreads();

#pragma unroll
        for (int ks = 0; ks < BK / 16; ks++) {
            const int kb = ks * 16 + lc * 2;

            uint32_t ah[4][4], al[4][4];
#pragma unroll
            for (int i = 0; i < 4; i++) {
                int r0 = warp_m * 64 + i * 16 + lr;
                const __nv_bfloat16* pa0 = sm + (size_t)r0 * ASTRIDE + kb;
                const __nv_bfloat16* pa1 = sm + (size_t)(r0 + 8) * ASTRIDE + kb;
                ah[i][0] = *(const uint32_t*)(pa0 + SM_AH);
                ah[i][1] = *(const uint32_t*)(pa1 + SM_AH);
                ah[i][2] = *(const uint32_t*)(pa0 + SM_AH + 8);
                ah[i][3] = *(const uint32_t*)(pa1 + SM_AH + 8);
                al[i][0] = *(const uint32_t*)(pa0 + SM_AL);
                al[i][1] = *(const uint32_t*)(pa1 + SM_AL);
                al[i][2] = *(const uint32_t*)(pa0 + SM_AL + 8);
                al[i][3] = *(const uint32_t*)(pa1 + SM_AL + 8);
            }
            uint32_t bh[4][2], bl[4][2];
#pragma unroll
            for (int j = 0; j < 4; j++) {
                int n0 = warp_n * 32 + j * 8 + lr;
                const __nv_bfloat16* pb = sm + (size_t)n0 * ASTRIDE + kb;
                bh[j][0] = *(const uint32_t*)(pb + SM_BH);
                bh[j][1] = *(const uint32_t*)(pb + SM_BH + 8);
                bl[j][0] = *(const uint32_t*)(pb + SM_BL);
                bl[j][1] = *(const uint32_t*)(pb + SM_BL + 8);
            }

#pragma unroll
            for (int i = 0; i < 4; i++)
#pragma unroll
                for (int j = 0; j < 4; j++) {
                    mma16816(acc[i][j], ah[i], bh[j]);
                    mma16816(acc[i][j], ah[i], bl[j]);
                    mma16816(acc[i][j], al[i], bh[j]);
                }
        }
        __syncthreads();
    }

#pragma unroll
    for (int j = 0; j < 4; j++) {
        int col = bn + warp_n * 32 + j * 8 + lc * 2;
        float b0 = __ldg(&bias[col]);
        float b1 = __ldg(&bias[col + 1]);
#pragma unroll
        for (int i = 0; i < 4; i++) {
            int r0 = bm + warp_m * 64 + i * 16 + lr;
            float2 v0 = { acc[i][j][0] + b0, acc[i][j][1] + b1 };
            float2 v1 = { acc[i][j][2] + b0, acc[i][j][3] + b1 };
            *(float2*)&g_incur[(size_t)r0 * NN + col]       = v0;
            *(float2*)&g_incur[(size_t)(r0 + 8) * NN + col] = v1;
        }
    }
}

// ===========================================================================
// Time-chunked speculative scan (zero-spike linear recurrence).
// R11 showed one-thread-per-neuron-over-full-T is latency-bound at 6.2% occ
// (only 16K threads). The recurrence is affine, so chunk T into NCHUNK
// pieces: u_end = decay^CLEN * u_in + f_chunk(0). Parallelism rises 20x.
//
// Phase A: per (b, n-pair, chunk) compute f_chunk(0) end state.  327,680 thr.
// Phase B: per (b, n-pair) chain the 20 chunk entry states.       16,384 thr.
// Phase C: per (b, n-pair, chunk) replay from u_in, emit outputs. 327,680 thr.
// Spike => g_flag[b]; gated exact fallback redoes that batch.
// ===========================================================================
__global__ __launch_bounds__(256) void scanA_kernel() {
    const int idx = blockIdx.x * 256 + threadIdx.x;       // 0..327679
    const int c   = idx / (BATCH * 256);                  // chunk
    const int r   = idx % (BATCH * 256);
    const int b   = r >> 8;
    const int n2  = (r & 255) << 1;

    const float decay = expf(-DT_F / TAU_F);
    const float omd   = 1.0f - decay;

    const float* curp = g_incur + (size_t)b * TT * NN + (size_t)c * CLEN * NN + n2;

    float u0 = 0.0f, u1 = 0.0f;
#pragma unroll 5
    for (int i = 0; i < CLEN; i++) {
        float2 cv = __ldcs((const float2*)(curp + (size_t)i * NN));
        u0 = decay * u0 + omd * cv.x;
        u1 = decay * u1 + omd * cv.y;
    }
    float2 ue; ue.x = u0; ue.y = u1;
    *(float2*)&g_uend[((size_t)c * BATCH + b) * NN + n2] = ue;
}

__global__ __launch_bounds__(256) void scanB_kernel() {
    const int idx = blockIdx.x * 256 + threadIdx.x;       // 0..16383
    const int b   = idx >> 8;
    const int n2  = (idx & 255) << 1;

    const float dL = expf(-(float)CLEN * DT_F / TAU_F);   // decay^CLEN

    float u0 = 0.0f, u1 = 0.0f;
#pragma unroll
    for (int c = 0; c < NCHUNK; c++) {
        float2 ui; ui.x = u0; ui.y = u1;
        *(float2*)&g_uin[((size_t)c * BATCH + b) * NN + n2] = ui;
        float2 ue = *(const float2*)&g_uend[((size_t)c * BATCH + b) * NN + n2];
        u0 = dL * u0 + ue.x;
        u1 = dL * u1 + ue.y;
    }
}

__global__ __launch_bounds__(256) void scanC_kernel(float* __restrict__ out) {
    const int idx = blockIdx.x * 256 + threadIdx.x;
    const int c   = idx / (BATCH * 256);
    const int r   = idx % (BATCH * 256);
    const int b   = r >> 8;
    const int n2  = (r & 255) << 1;

    float* outs  = out;                                        // [B][T][N]
    float* u_all = out + (size_t)BATCH * TT * NN;              // [B][T+1][N]
    float* z_all = u_all + (size_t)BATCH * (TT + 1) * NN;      // [B][T+1][N]

    const float decay = expf(-DT_F / TAU_F);
    const float omd   = 1.0f - decay;

    const int t0 = c * CLEN;
    const size_t ob = (size_t)b * TT * NN + (size_t)t0 * NN + n2;
    const size_t ub = (size_t)b * (TT + 1) * NN + (size_t)(t0 + 1) * NN + n2;

    // chunk 0 threads also write the t=0 zero states
    if (c == 0) {
        float2 zz; zz.x = 0.0f; zz.y = 0.0f;
        __stcs((float2*)&u_all[(size_t)b * (TT + 1) * NN + n2], zz);
        __stcs((float2*)&z_all[(size_t)b * (TT + 1) * NN + n2], zz);
    }

    float2 ui = *(const float2*)&g_uin[((size_t)c * BATCH + b) * NN + n2];
    float u0 = ui.x, u1 = ui.y;
    bool spiked = false;

    const float* curp = g_incur + (size_t)b * TT * NN + (size_t)t0 * NN + n2;

#pragma unroll 5
    for (int i = 0; i < CLEN; i++) {
        float2 cv = __ldcs((const float2*)(curp + (size_t)i * NN));
        u0 = decay * u0 + omd * cv.x;
        u1 = decay * u1 + omd * cv.y;
        float z0 = (u0 - THR_F > 0.0f) ? 1.0f : 0.0f;
        float z1 = (u1 - THR_F > 0.0f) ? 1.0f : 0.0f;
        spiked = spiked || (z0 != 0.0f) || (z1 != 0.0f);

        float2 zv; zv.x = z0; zv.y = z1;
        float2 uv; uv.x = u0; uv.y = u1;
        __stcs((float2*)&outs[ob + (size_t)i * NN], zv);
        __stcs((float2*)&u_all[ub + (size_t)i * NN], uv);
        __stcs((float2*)&z_all[ub + (size_t)i * NN], zv);
    }

    if (spiked) g_flag[b] = 1;
}

// ===========================================================================
// Exact fallback scan, gated per batch (unchanged, proven)
// ===========================================================================
__global__ __launch_bounds__(NN) void fallback_scan_kernel(float* __restrict__ out) {
    const int b = blockIdx.x;
    if (g_flag[b] == 0) return;

    const int n = threadIdx.x;
    const int lane = n & 31;
    const int warp = n >> 5;

    __shared__ __align__(16) unsigned mask[2][16];

    float* outs  = out;
    float* u_all = out + (size_t)BATCH * TT * NN;
    float* z_all = u_all + (size_t)BATCH * (TT + 1) * NN;

    __stcs(&u_all[(size_t)b * (TT + 1) * NN + n], 0.0f);
    __stcs(&z_all[(size_t)b * (TT + 1) * NN + n], 0.0f);

    const float decay = expf(-DT_F / TAU_F);
    const float omd   = 1.0f - decay;

    const float* curp = g_incur + (size_t)b * TT * NN + n;

    float u = 0.0f;
    float z = 0.0f;
    float cur = __ldcs(curp);

    for (int t = 0; t < TT; t++) {
        float cur_next = (t + 1 < TT) ? __ldcs(curp + (size_t)(t + 1) * NN) : 0.0f;

        const int any = __syncthreads_or(z != 0.0f);

        const int p = t & 1;
        float rec = 0.0f;
        if (any) {
#pragma unroll
            for (int w = 0; w < 16; w++) {
                unsigned bits = mask[p][w];
                while (bits) {
                    int j = (w << 5) + __ffs((int)bits) - 1;
                    rec += g_Rt[(size_t)j * NN + n];
                    bits &= bits - 1;
                }
            }
        }

        u = u * (1.0f - z);
        float soma = cur + rec;
        u = decay * u + omd * soma;
        z = (u - THR_F > 0.0f) ? 1.0f : 0.0f;

        unsigned bal = __ballot_sync(0xffffffffu, z != 0.0f);
        if (lane == 0) mask[1 - p][warp] = bal;

        size_t oidx = (size_t)b * TT * NN + (size_t)t * NN + n;
        __stcs(&outs[oidx], z);
        size_t sidx = (size_t)b * (TT + 1) * NN + (size_t)(t + 1) * NN + n;
        __stcs(&u_all[sidx], u);
        __stcs(&z_all[sidx], z);

        cur = cur_next;
    }
}

// ===========================================================================
// Launch
// ===========================================================================
extern "C" void kernel_launch(void* const* d_in, const int* in_sizes, int n_in,
                              void* d_out, int out_size) {
    const float* x = nullptr;    // 16,384,000
    const float* W = nullptr;    // 131,072
    const float* bias = nullptr; // 512
    const float* R = nullptr;    // 262,144
    for (int i = 0; i < n_in; i++) {
        switch (in_sizes[i]) {
            case 16384000: x = (const float*)d_in[i]; break;
            case 131072:   W = (const float*)d_in[i]; break;
            case 512:      bias = (const float*)d_in[i]; break;
            case 262144:   R = (const float*)d_in[i]; break;
            default: break;
        }
    }

    cudaFuncSetAttribute(gemm_hmma_kernel,
                         cudaFuncAttributeMaxDynamicSharedMemorySize, HMMA_SMEM);

    // 1) Transpose R -> Rt and clear speculation flags
    dim3 tb(32, 32), tg(NN / 32, NN / 32);
    transpose_R_kernel<<<tg, tb>>>(R);

    // 2) Split x, W into bf16 hi/lo pairs
    split_kernel<<<16128, 256>>>(x, W);

    // 3) HMMA GEMM (3x bf16 mma.sync, fp32 accum) -> g_incur
    gemm_hmma_kernel<<<dim3(MROWS / 128, NN / 128), 256, HMMA_SMEM>>>(bias);

    // 4) Time-chunked speculative scan: A (chunk ends), B (chain), C (emit)
    const int PAR = NCHUNK * BATCH * 256;     // 327,680 threads
    scanA_kernel<<<PAR / 256, 256>>>();
    scanB_kernel<<<BATCH * 256 / 256, 256>>>();
    scanC_kernel<<<PAR / 256, 256>>>((float*)d_out);

    // 5) Exact fallback, gated per batch (no-op when speculation held)
    fallback_scan_kernel<<<BATCH, NN>>>((float*)d_out);
}